// round 9
// baseline (speedup 1.0000x reference)
#include <cuda_runtime.h>
#include <mma.h>
#include <cstdint>

using namespace nvcuda;

// Problem constants
#define BSZ   64
#define PP    512
#define DWM   1024
#define WIN   128
#define MROWS (BSZ * PP)   // 32768
#define TQ    8

// ---------------------------------------------------------------------------
// Scratch (device globals — no allocation allowed)
// ---------------------------------------------------------------------------
__device__ float g_q [(size_t)MROWS * DWM];
__device__ float g_k [(size_t)MROWS * DWM];
__device__ float g_v [(size_t)MROWS * DWM];
__device__ float g_o [(size_t)MROWS * DWM];   // attention out (tf32-rounded)
__device__ float g_xr[(size_t)MROWS * DWM];   // x rounded to tf32
__device__ float g_w [(size_t)4 * 1024 * 1024]; // 4 weights [K,N], tf32-rounded
__device__ float g_bias[4 * 1024];
__device__ int   g_start[BSZ * PP];

// ---------------------------------------------------------------------------
// Helpers (portable PTX only — compute_103 virtual arch, no tcgen05)
// ---------------------------------------------------------------------------
__device__ __forceinline__ float ftf32(float x) {
    uint32_t u;
    asm("cvt.rn.tf32.f32 %0, %1;" : "=r"(u) : "f"(x));
    return __uint_as_float(u);
}
__device__ __forceinline__ uint32_t smem_u32(const void* p) {
    uint32_t a;
    asm("{ .reg .u64 t; cvta.to.shared.u64 t, %1; cvt.u32.u64 %0, t; }" : "=r"(a) : "l"(p));
    return a;
}
#define CP16(d, s)  asm volatile("cp.async.cg.shared.global [%0], [%1], 16;" :: "r"(d), "l"(s) : "memory")
#define CP_COMMIT() asm volatile("cp.async.commit_group;" ::: "memory")
#define CP_WAIT1()  asm volatile("cp.async.wait_group 1;" ::: "memory")

// ---------------------------------------------------------------------------
// Prep: reset-mask dtype probe + window start indices + bias copy
// ---------------------------------------------------------------------------
__global__ void prep_kernel(const unsigned char* __restrict__ reset_raw,
                            const float* __restrict__ bq, const float* __restrict__ bk,
                            const float* __restrict__ bv, const float* __restrict__ bo)
{
    __shared__ int s_ni, s_nf, s_any;
    if (threadIdx.x == 0) { s_ni = 0; s_nf = 0; s_any = 0; }
    __syncthreads();
    const unsigned int* w32 = (const unsigned int*)reset_raw;
    int ni = 0, nf = 0, any = 0;
    for (int i = threadIdx.x; i < 8192; i += blockDim.x) {   // 32768 bytes, safe all dtypes
        unsigned int v = w32[i];
        if (v != 0u) {
            any = 1;
            if (v != 1u)          ni = 1;
            if (v != 0x3f800000u) nf = 1;
        }
    }
    if (ni)  atomicOr(&s_ni, 1);
    if (nf)  atomicOr(&s_nf, 1);
    if (any) atomicOr(&s_any, 1);
    __syncthreads();
    int mode;
    if (!s_any)      mode = -1;
    else if (!s_ni)  mode = 1;
    else if (!s_nf)  mode = 2;
    else             mode = 0;

    for (int b = threadIdx.x; b < BSZ; b += blockDim.x) {
        int r = 0;
        for (int t = 0; t < PP; t++) {
            int idx = b * PP + t;
            bool reset = false;
            if (mode == 0)      reset = (reset_raw[idx] != 0);
            else if (mode > 0)  reset = (w32[idx] != 0u);
            if (reset) r = t;
            int s = t - (WIN - 1);
            if (s < r) s = r;
            if (s < 0) s = 0;
            g_start[idx] = s;
        }
    }
    for (int i = threadIdx.x; i < 1024; i += blockDim.x) {
        g_bias[i]        = bq[i];
        g_bias[1024 + i] = bk[i];
        g_bias[2048 + i] = bv[i];
        g_bias[3072 + i] = bo[i];
    }
}

// ---------------------------------------------------------------------------
// Round x to tf32 once (HMMA truncation then a no-op -> RN numerics)
// ---------------------------------------------------------------------------
__global__ void round_x_kernel(const float4* __restrict__ x)
{
    size_t i = (size_t)blockIdx.x * blockDim.x + threadIdx.x;
    float4 v = x[i];
    v.x = ftf32(v.x); v.y = ftf32(v.y); v.z = ftf32(v.z); v.w = ftf32(v.w);
    reinterpret_cast<float4*>(g_xr)[i] = v;
}

// Round the 4 weights to tf32 (layout kept [K,N] — row_major B for wmma)
__global__ void round_w_kernel(const float4* __restrict__ W0, const float4* __restrict__ W1,
                               const float4* __restrict__ W2, const float4* __restrict__ W3)
{
    const float4* W = (blockIdx.y == 0) ? W0 : (blockIdx.y == 1) ? W1
                    : (blockIdx.y == 2) ? W2 : W3;
    size_t i = (size_t)blockIdx.x * blockDim.x + threadIdx.x;   // 0..262143
    float4 v = W[i];
    v.x = ftf32(v.x); v.y = ftf32(v.y); v.z = ftf32(v.z); v.w = ftf32(v.w);
    reinterpret_cast<float4*>(g_w)[(size_t)blockIdx.y * 262144 + i] = v;
}

// ---------------------------------------------------------------------------
// Pipelined TF32 WMMA GEMM: C[32768,1024] = A @ W + bias
// Block tile 128x128, K-tile 32, 3-stage cp.async ring (ONE barrier per
// k-tile), 8 warps (4Mx2N), warp tile 32x64.
// Smem strides are = 4 (mod 32 banks) -> conflict-free/2-way fragment loads
// (stride = 8 mod 32 was the Round-7 bottleneck: 4-way conflicts, tensor 53%).
//   asel:  0 -> A = g_xr, 1 -> A = g_o
//   wbase: weight/bias/C base index (0 for fused QKV, 3 for output proj)
// ---------------------------------------------------------------------------
#define GBK   32
#define LDAp  36            // 32 + 4 pad  (=4 mod 32 banks; 144B rows, 16B-aligned)
#define LDBp  132           // 128 + 4 pad (=4 mod 32 banks; 528B rows, 16B-aligned)
#define STG_A (128 * LDAp)              // 4608 floats
#define STG_F (STG_A + GBK * LDBp)      // 8832 floats per stage
#define STG_B_OFF (STG_A * 4)           // 18432 bytes
#define STG_BYTES (STG_F * 4)           // 35328 bytes
#define GSMEM (3 * STG_BYTES)           // 105984 bytes (2 CTAs/SM: 207KB < 228KB)

__global__ __launch_bounds__(256, 2)
void gemm_tf32_kernel(float* __restrict__ Cext, int asel, int wbase)
{
    extern __shared__ float smem[];
    const uint32_t sb = smem_u32(smem);
    const int tid = threadIdx.x, warp = tid >> 5, lane = tid & 31;
    const int w  = wbase + (blockIdx.x >> 3);
    const int bn = blockIdx.x & 7;
    const int bm = blockIdx.y;
    const int wm = warp & 3;      // 4 warps along M
    const int wn = warp >> 2;     // 2 warps along N

    const float* A  = asel ? g_o : g_xr;
    const float* Bw = g_w + (size_t)w * 1048576 + bn * 128;
    float* C = (w == 0) ? g_q : (w == 1) ? g_k : (w == 2) ? g_v : Cext;
    const float* bias = g_bias + w * 1024;

    const float* Ab = A + (size_t)bm * 128 * 1024;

    // Per-thread cp.async plan: 4 A-chunks + 4 B-chunks of 16B per k-tile
    const float* asrc[4]; const float* bsrc[4];
    uint32_t aoff[4], boff[4];
#pragma unroll
    for (int i = 0; i < 4; i++) {
        int idx = tid + i * 256;
        {   // A tile: 128 rows x 32 cols
            int r = idx >> 3, c4 = idx & 7;
            asrc[i] = Ab + (size_t)r * 1024 + c4 * 4;
            aoff[i] = (uint32_t)(r * LDAp + c4 * 4) * 4;
        }
        {   // B tile: 32 rows (K) x 128 cols (N)
            int r = idx >> 5, c4 = idx & 31;
            bsrc[i] = Bw + (size_t)r * 1024 + c4 * 4;
            boff[i] = STG_B_OFF + (uint32_t)(r * LDBp + c4 * 4) * 4;
        }
    }

    wmma::fragment<wmma::accumulator, 16, 16, 8, float> acc[2][4];
#pragma unroll
    for (int mi = 0; mi < 2; mi++)
#pragma unroll
        for (int ni = 0; ni < 4; ni++)
            wmma::fill_fragment(acc[mi][ni], 0.0f);

    // Prologue: tiles 0,1 -> stages 0,1 (two commit groups)
#pragma unroll
    for (int t = 0; t < 2; t++) {
        uint32_t st = sb + t * STG_BYTES;
#pragma unroll
        for (int i = 0; i < 4; i++) CP16(st + aoff[i], asrc[i] + t * 32);
#pragma unroll
        for (int i = 0; i < 4; i++) CP16(st + boff[i], bsrc[i] + (size_t)t * 32 * 1024);
        CP_COMMIT();
    }

    int s = 0;                 // stage of tile t
    for (int t = 0; t < 32; t++) {
        CP_WAIT1();            // tile t landed (this thread); <=1 group pending
        __syncthreads();       // ...for all threads; also orders: every warp has
                               // finished computing tile t-1, so the prefetch
                               // below may safely overwrite stage (t+2)%3=(t-1)%3

        const float* sA  = smem + s * STG_F;
        const float* sBt = sA + STG_A;
#pragma unroll
        for (int kk = 0; kk < GBK; kk += 8) {
            wmma::fragment<wmma::matrix_a, 16, 16, 8, wmma::precision::tf32, wmma::row_major> af[2];
            wmma::fragment<wmma::matrix_b, 16, 16, 8, wmma::precision::tf32, wmma::row_major> bf[4];
#pragma unroll
            for (int mi = 0; mi < 2; mi++)
                wmma::load_matrix_sync(af[mi], sA + (wm * 32 + mi * 16) * LDAp + kk, LDAp);
#pragma unroll
            for (int ni = 0; ni < 4; ni++)
                wmma::load_matrix_sync(bf[ni], sBt + kk * LDBp + wn * 64 + ni * 16, LDBp);
            // operands pre-rounded to tf32 -> no per-element cvt needed
#pragma unroll
            for (int mi = 0; mi < 2; mi++)
#pragma unroll
                for (int ni = 0; ni < 4; ni++)
                    wmma::mma_sync(acc[mi][ni], af[mi], bf[ni], acc[mi][ni]);
        }

        // Prefetch tile t+2 into stage (t+2)%3 (empty commit keeps counts uniform)
        const int tp = t + 2;
        if (tp < 32) {
            int sp = s + 2; if (sp >= 3) sp -= 3;
            uint32_t st = sb + sp * STG_BYTES;
#pragma unroll
            for (int i = 0; i < 4; i++) CP16(st + aoff[i], asrc[i] + tp * 32);
#pragma unroll
            for (int i = 0; i < 4; i++) CP16(st + boff[i], bsrc[i] + (size_t)tp * 32 * 1024);
        }
        CP_COMMIT();

        if (++s == 3) s = 0;
    }
    __syncthreads();   // protect smem scratch reuse below from in-flight readers

    // Epilogue: per-warp 16x16 scratch roundtrip, bias add, float4 stores
    float* myC = smem + warp * 16 * 20;
    const int r  = lane >> 1;
    const int ch = (lane & 1) * 8;
#pragma unroll
    for (int mi = 0; mi < 2; mi++)
#pragma unroll
        for (int ni = 0; ni < 4; ni++) {
            wmma::store_matrix_sync(myC, acc[mi][ni], 20, wmma::mem_row_major);
            __syncwarp();
            int gm = bm * 128 + wm * 32 + mi * 16 + r;
            int gn = bn * 128 + wn * 64 + ni * 16 + ch;
            float4 o0, o1;
            o0.x = myC[r * 20 + ch + 0] + bias[gn + 0];
            o0.y = myC[r * 20 + ch + 1] + bias[gn + 1];
            o0.z = myC[r * 20 + ch + 2] + bias[gn + 2];
            o0.w = myC[r * 20 + ch + 3] + bias[gn + 3];
            o1.x = myC[r * 20 + ch + 4] + bias[gn + 4];
            o1.y = myC[r * 20 + ch + 5] + bias[gn + 5];
            o1.z = myC[r * 20 + ch + 6] + bias[gn + 6];
            o1.w = myC[r * 20 + ch + 7] + bias[gn + 7];
            *(float4*)(C + (size_t)gm * 1024 + gn)     = o0;
            *(float4*)(C + (size_t)gm * 1024 + gn + 4) = o1;
            __syncwarp();
        }
}

// ---------------------------------------------------------------------------
// Sliding-window attention with doc resets, online softmax.
// Block = (batch b, tile of TQ=8 queries). Warp w owns heads 2w,2w+1;
// 16 lanes/head, 4 head-dims/lane. Output tf32-rounded for the final GEMM.
// ---------------------------------------------------------------------------
__global__ __launch_bounds__(256)
void attn_kernel()
{
    const int b    = blockIdx.x;
    const int tb   = blockIdx.y * TQ;
    const int warp = threadIdx.x >> 5;
    const int lane = threadIdx.x & 31;
    const int h    = warp * 2 + (lane >> 4);
    const int sub  = lane & 15;
    const int d0   = h * 64 + sub * 4;

    const float* qb = g_q + (size_t)b * PP * DWM;
    const float* kb = g_k + (size_t)b * PP * DWM;
    const float* vb = g_v + (size_t)b * PP * DWM;
    float*       ob = g_o + (size_t)b * PP * DWM;

    const float NEG_INF = __int_as_float(0xff800000);

    float4 q4[TQ], acc[TQ];
    float  m[TQ], l[TQ];
    int    st[TQ];
#pragma unroll
    for (int i = 0; i < TQ; i++) {
        int t = tb + i;
        q4[i]  = *(const float4*)(qb + (size_t)t * DWM + d0);
        st[i]  = g_start[b * PP + t];
        m[i]   = NEG_INF;
        l[i]   = 0.0f;
        acc[i] = make_float4(0.f, 0.f, 0.f, 0.f);
    }

    const int jmin = st[0];            // start index monotone in t
    const int jmax = tb + TQ - 1;

    for (int j = jmin; j <= jmax; j++) {
        float4 k4 = *(const float4*)(kb + (size_t)j * DWM + d0);
        float4 v4 = *(const float4*)(vb + (size_t)j * DWM + d0);
        float s[TQ];
#pragma unroll
        for (int i = 0; i < TQ; i++)
            s[i] = q4[i].x * k4.x + q4[i].y * k4.y + q4[i].z * k4.z + q4[i].w * k4.w;
#pragma unroll
        for (int off = 8; off >= 1; off >>= 1)
#pragma unroll
            for (int i = 0; i < TQ; i++)
                s[i] += __shfl_xor_sync(0xffffffffu, s[i], off, 16);

#pragma unroll
        for (int i = 0; i < TQ; i++) {
            int t = tb + i;
            if (j >= st[i] && j <= t) {
                float sc = s[i] * 0.125f;
                float mn = fmaxf(m[i], sc);
                float co = __expf(m[i] - mn);
                float wt = __expf(sc - mn);
                l[i] = l[i] * co + wt;
                acc[i].x = acc[i].x * co + wt * v4.x;
                acc[i].y = acc[i].y * co + wt * v4.y;
                acc[i].z = acc[i].z * co + wt * v4.z;
                acc[i].w = acc[i].w * co + wt * v4.w;
                m[i] = mn;
            }
        }
    }

#pragma unroll
    for (int i = 0; i < TQ; i++) {
        float inv = 1.0f / l[i];
        float4 o = make_float4(ftf32(acc[i].x * inv), ftf32(acc[i].y * inv),
                               ftf32(acc[i].z * inv), ftf32(acc[i].w * inv));
        *(float4*)(ob + (size_t)(tb + i) * DWM + d0) = o;
    }
}

// ---------------------------------------------------------------------------
// Launch
// ---------------------------------------------------------------------------
extern "C" void kernel_launch(void* const* d_in, const int* in_sizes, int n_in,
                              void* d_out, int out_size)
{
    const float*         x  = (const float*)d_in[0];
    const unsigned char* rs = (const unsigned char*)d_in[1];
    const float* Wq = (const float*)d_in[2];
    const float* bq = (const float*)d_in[3];
    const float* Wk = (const float*)d_in[4];
    const float* bk = (const float*)d_in[5];
    const float* Wv = (const float*)d_in[6];
    const float* bv = (const float*)d_in[7];
    const float* Wo = (const float*)d_in[8];
    const float* bo = (const float*)d_in[9];
    float* y = (float*)d_out;

    cudaFuncSetAttribute(gemm_tf32_kernel,
                         cudaFuncAttributeMaxDynamicSharedMemorySize, GSMEM);

    prep_kernel<<<1, 256>>>(rs, bq, bk, bv, bo);
    round_x_kernel<<<32768, 256>>>((const float4*)x);
    round_w_kernel<<<dim3(1024, 4), 256>>>((const float4*)Wq, (const float4*)Wk,
                                           (const float4*)Wv, (const float4*)Wo);

    // Fused Q,K,V projections: grid.x = 3 weights * 8 bn (bn fast -> A stripe
    // shared by 24 CTAs, weights L2-resident)
    gemm_tf32_kernel<<<dim3(24, 256), 256, GSMEM>>>(nullptr, 0, 0);

    attn_kernel<<<dim3(BSZ, PP / TQ), 256>>>();

    // y = attn_out @ Wo + bo
    gemm_tf32_kernel<<<dim3(8, 256), 256, GSMEM>>>(y, 1, 3);
}

// round 10
// speedup vs baseline: 2.6325x; 2.6325x over previous
#include <cuda_runtime.h>
#include <cuda_fp16.h>
#include <mma.h>
#include <cstdint>

using namespace nvcuda;

// Problem constants
#define BSZ   64
#define PP    512
#define DWM   1024
#define WIN   128
#define MROWS (BSZ * PP)   // 32768
#define TQ    8

// ---------------------------------------------------------------------------
// Scratch (device globals — no allocation allowed)
// ---------------------------------------------------------------------------
__device__ float  g_q [(size_t)MROWS * DWM];
__device__ float  g_k [(size_t)MROWS * DWM];
__device__ float  g_v [(size_t)MROWS * DWM];
__device__ __half g_o [(size_t)MROWS * DWM];    // attention out (half)
__device__ __half g_xh[(size_t)MROWS * DWM];    // x in half
__device__ __half g_w [(size_t)4 * 1024 * 1024]; // 4 weights [K,N], half
__device__ float  g_bias[4 * 1024];
__device__ int    g_start[BSZ * PP];

// ---------------------------------------------------------------------------
// Helpers (portable PTX only — compute_103 virtual arch, no tcgen05)
// ---------------------------------------------------------------------------
__device__ __forceinline__ uint32_t smem_u32(const void* p) {
    uint32_t a;
    asm("{ .reg .u64 t; cvta.to.shared.u64 t, %1; cvt.u32.u64 %0, t; }" : "=r"(a) : "l"(p));
    return a;
}
#define CP16(d, s)  asm volatile("cp.async.cg.shared.global [%0], [%1], 16;" :: "r"(d), "l"(s) : "memory")
#define CP_COMMIT() asm volatile("cp.async.commit_group;" ::: "memory")
#define CP_WAIT1()  asm volatile("cp.async.wait_group 1;" ::: "memory")

// ---------------------------------------------------------------------------
// Prep: reset-mask dtype probe + window start indices + bias copy
// ---------------------------------------------------------------------------
__global__ void prep_kernel(const unsigned char* __restrict__ reset_raw,
                            const float* __restrict__ bq, const float* __restrict__ bk,
                            const float* __restrict__ bv, const float* __restrict__ bo)
{
    __shared__ int s_ni, s_nf, s_any;
    if (threadIdx.x == 0) { s_ni = 0; s_nf = 0; s_any = 0; }
    __syncthreads();
    const unsigned int* w32 = (const unsigned int*)reset_raw;
    int ni = 0, nf = 0, any = 0;
    for (int i = threadIdx.x; i < 8192; i += blockDim.x) {   // 32768 bytes, safe all dtypes
        unsigned int v = w32[i];
        if (v != 0u) {
            any = 1;
            if (v != 1u)          ni = 1;
            if (v != 0x3f800000u) nf = 1;
        }
    }
    if (ni)  atomicOr(&s_ni, 1);
    if (nf)  atomicOr(&s_nf, 1);
    if (any) atomicOr(&s_any, 1);
    __syncthreads();
    int mode;
    if (!s_any)      mode = -1;
    else if (!s_ni)  mode = 1;
    else if (!s_nf)  mode = 2;
    else             mode = 0;

    for (int b = threadIdx.x; b < BSZ; b += blockDim.x) {
        int r = 0;
        for (int t = 0; t < PP; t++) {
            int idx = b * PP + t;
            bool reset = false;
            if (mode == 0)      reset = (reset_raw[idx] != 0);
            else if (mode > 0)  reset = (w32[idx] != 0u);
            if (reset) r = t;
            int s = t - (WIN - 1);
            if (s < r) s = r;
            if (s < 0) s = 0;
            g_start[idx] = s;
        }
    }
    for (int i = threadIdx.x; i < 1024; i += blockDim.x) {
        g_bias[i]        = bq[i];
        g_bias[1024 + i] = bk[i];
        g_bias[2048 + i] = bv[i];
        g_bias[3072 + i] = bo[i];
    }
}

// ---------------------------------------------------------------------------
// Convert x to half (one RN rounding; fp16 mantissa = tf32 mantissa = 10 bits)
// ---------------------------------------------------------------------------
__global__ void conv_x_kernel(const float4* __restrict__ x)
{
    size_t i = (size_t)blockIdx.x * blockDim.x + threadIdx.x;
    float4 v = x[i];
    __half2 p0 = __floats2half2_rn(v.x, v.y);
    __half2 p1 = __floats2half2_rn(v.z, v.w);
    __half2* dst = reinterpret_cast<__half2*>(g_xh) + 2 * i;
    dst[0] = p0; dst[1] = p1;
}

// Convert the 4 weights to half (layout kept [K,N] — row_major B for wmma)
__global__ void conv_w_kernel(const float4* __restrict__ W0, const float4* __restrict__ W1,
                              const float4* __restrict__ W2, const float4* __restrict__ W3)
{
    const float4* W = (blockIdx.y == 0) ? W0 : (blockIdx.y == 1) ? W1
                    : (blockIdx.y == 2) ? W2 : W3;
    size_t i = (size_t)blockIdx.x * blockDim.x + threadIdx.x;   // 0..262143
    float4 v = W[i];
    __half2 p0 = __floats2half2_rn(v.x, v.y);
    __half2 p1 = __floats2half2_rn(v.z, v.w);
    __half2* dst = reinterpret_cast<__half2*>(g_w) + (size_t)blockIdx.y * 524288 + 2 * i;
    dst[0] = p0; dst[1] = p1;
}

// ---------------------------------------------------------------------------
// Pipelined FP16 WMMA GEMM: C[32768,1024](f32) = A(h) @ W(h) + bias
// Block tile 128x128, K-tile 32, 3-stage cp.async ring (one barrier per
// k-tile), 8 warps (4Mx2N), warp tile 32x64, wmma m16n16k16 f32-accum.
//   asel:  0 -> A = g_xh, 1 -> A = g_o
//   wbase: weight/bias/C base index (0 for fused QKV, 3 for output proj)
// ---------------------------------------------------------------------------
#define GBK   32
#define LDAh  40            // halves: 32 + 8 pad (80B rows, 16B-aligned)
#define LDBh  136           // halves: 128 + 8 pad (272B rows, 16B-aligned)
#define STG_AH    (128 * LDAh)            // 5120 halves
#define STG_B_OFF (STG_AH * 2)            // 10240 bytes
#define STG_BYTES (STG_B_OFF + GBK * LDBh * 2)   // 18944 bytes
#define GSMEM (3 * STG_BYTES)             // 56832 bytes (2 CTAs/SM easily)

__global__ __launch_bounds__(256, 2)
void gemm_fp16_kernel(float* __restrict__ Cext, int asel, int wbase)
{
    extern __shared__ char smemraw[];
    const uint32_t sb = smem_u32(smemraw);
    const int tid = threadIdx.x, warp = tid >> 5, lane = tid & 31;
    const int w  = wbase + (blockIdx.x >> 3);
    const int bn = blockIdx.x & 7;
    const int bm = blockIdx.y;
    const int wm = warp & 3;      // 4 warps along M
    const int wn = warp >> 2;     // 2 warps along N

    const __half* A  = asel ? g_o : g_xh;
    const __half* Bw = g_w + (size_t)w * 1048576 + bn * 128;
    float* C = (w == 0) ? g_q : (w == 1) ? g_k : (w == 2) ? g_v : Cext;
    const float* bias = g_bias + w * 1024;

    const __half* Ab = A + (size_t)bm * 128 * 1024;

    // Per-thread cp.async plan: 2 A-chunks + 2 B-chunks of 16B (8 halves)
    const __half* asrc[2]; const __half* bsrc[2];
    uint32_t aoff[2], boff[2];
#pragma unroll
    for (int i = 0; i < 2; i++) {
        int idx = tid + i * 256;   // 0..511
        {   // A tile: 128 rows x 32 halves (4 chunks/row)
            int r = idx >> 2, c = idx & 3;
            asrc[i] = Ab + (size_t)r * 1024 + c * 8;
            aoff[i] = (uint32_t)(r * LDAh + c * 8) * 2;
        }
        {   // B tile: 32 rows (K) x 128 halves (16 chunks/row)
            int r = idx >> 4, c = idx & 15;
            bsrc[i] = Bw + (size_t)r * 1024 + c * 8;
            boff[i] = STG_B_OFF + (uint32_t)(r * LDBh + c * 8) * 2;
        }
    }

    wmma::fragment<wmma::accumulator, 16, 16, 16, float> acc[2][4];
#pragma unroll
    for (int mi = 0; mi < 2; mi++)
#pragma unroll
        for (int ni = 0; ni < 4; ni++)
            wmma::fill_fragment(acc[mi][ni], 0.0f);

    // Prologue: tiles 0,1 -> stages 0,1 (two commit groups)
#pragma unroll
    for (int t = 0; t < 2; t++) {
        uint32_t st = sb + t * STG_BYTES;
#pragma unroll
        for (int i = 0; i < 2; i++) CP16(st + aoff[i], asrc[i] + t * 32);
#pragma unroll
        for (int i = 0; i < 2; i++) CP16(st + boff[i], bsrc[i] + (size_t)t * 32 * 1024);
        CP_COMMIT();
    }

    int s = 0;                 // stage of tile t
    for (int t = 0; t < 32; t++) {
        CP_WAIT1();            // tile t landed (this thread); <=1 group pending
        __syncthreads();       // ...for all threads; also licenses overwriting
                               // stage (t+2)%3 == (t-1)%3 (consumed last iter)

        const __half* sA  = (const __half*)(smemraw + s * STG_BYTES);
        const __half* sBt = (const __half*)(smemraw + s * STG_BYTES + STG_B_OFF);
#pragma unroll
        for (int kk = 0; kk < GBK; kk += 16) {
            wmma::fragment<wmma::matrix_a, 16, 16, 16, __half, wmma::row_major> af[2];
            wmma::fragment<wmma::matrix_b, 16, 16, 16, __half, wmma::row_major> bf[4];
#pragma unroll
            for (int mi = 0; mi < 2; mi++)
                wmma::load_matrix_sync(af[mi], sA + (wm * 32 + mi * 16) * LDAh + kk, LDAh);
#pragma unroll
            for (int ni = 0; ni < 4; ni++)
                wmma::load_matrix_sync(bf[ni], sBt + kk * LDBh + wn * 64 + ni * 16, LDBh);
#pragma unroll
            for (int mi = 0; mi < 2; mi++)
#pragma unroll
                for (int ni = 0; ni < 4; ni++)
                    wmma::mma_sync(acc[mi][ni], af[mi], bf[ni], acc[mi][ni]);
        }

        // Prefetch tile t+2 into stage (t+2)%3 (empty commit keeps counts uniform)
        const int tp = t + 2;
        if (tp < 32) {
            int sp = s + 2; if (sp >= 3) sp -= 3;
            uint32_t st = sb + sp * STG_BYTES;
#pragma unroll
            for (int i = 0; i < 2; i++) CP16(st + aoff[i], asrc[i] + tp * 32);
#pragma unroll
            for (int i = 0; i < 2; i++) CP16(st + boff[i], bsrc[i] + (size_t)tp * 32 * 1024);
        }
        CP_COMMIT();

        if (++s == 3) s = 0;
    }
    __syncthreads();   // protect smem scratch reuse below

    // Epilogue: per-warp 16x16 scratch roundtrip (f32), bias add, float4 stores
    float* myC = (float*)smemraw + warp * 16 * 20;
    const int r  = lane >> 1;
    const int ch = (lane & 1) * 8;
#pragma unroll
    for (int mi = 0; mi < 2; mi++)
#pragma unroll
        for (int ni = 0; ni < 4; ni++) {
            wmma::store_matrix_sync(myC, acc[mi][ni], 20, wmma::mem_row_major);
            __syncwarp();
            int gm = bm * 128 + wm * 32 + mi * 16 + r;
            int gn = bn * 128 + wn * 64 + ni * 16 + ch;
            float4 o0, o1;
            o0.x = myC[r * 20 + ch + 0] + bias[gn + 0];
            o0.y = myC[r * 20 + ch + 1] + bias[gn + 1];
            o0.z = myC[r * 20 + ch + 2] + bias[gn + 2];
            o0.w = myC[r * 20 + ch + 3] + bias[gn + 3];
            o1.x = myC[r * 20 + ch + 4] + bias[gn + 4];
            o1.y = myC[r * 20 + ch + 5] + bias[gn + 5];
            o1.z = myC[r * 20 + ch + 6] + bias[gn + 6];
            o1.w = myC[r * 20 + ch + 7] + bias[gn + 7];
            *(float4*)(C + (size_t)gm * 1024 + gn)     = o0;
            *(float4*)(C + (size_t)gm * 1024 + gn + 4) = o1;
            __syncwarp();
        }
}

// ---------------------------------------------------------------------------
// Sliding-window attention with doc resets, online softmax (fp32 in, half out)
// Block = (batch b, tile of TQ=8 queries). Warp w owns heads 2w,2w+1;
// 16 lanes/head, 4 head-dims/lane.
// ---------------------------------------------------------------------------
__global__ __launch_bounds__(256)
void attn_kernel()
{
    const int b    = blockIdx.x;
    const int tb   = blockIdx.y * TQ;
    const int warp = threadIdx.x >> 5;
    const int lane = threadIdx.x & 31;
    const int h    = warp * 2 + (lane >> 4);
    const int sub  = lane & 15;
    const int d0   = h * 64 + sub * 4;

    const float* qb = g_q + (size_t)b * PP * DWM;
    const float* kb = g_k + (size_t)b * PP * DWM;
    const float* vb = g_v + (size_t)b * PP * DWM;
    __half*      ob = g_o + (size_t)b * PP * DWM;

    const float NEG_INF = __int_as_float(0xff800000);

    float4 q4[TQ], acc[TQ];
    float  m[TQ], l[TQ];
    int    st[TQ];
#pragma unroll
    for (int i = 0; i < TQ; i++) {
        int t = tb + i;
        q4[i]  = *(const float4*)(qb + (size_t)t * DWM + d0);
        st[i]  = g_start[b * PP + t];
        m[i]   = NEG_INF;
        l[i]   = 0.0f;
        acc[i] = make_float4(0.f, 0.f, 0.f, 0.f);
    }

    const int jmin = st[0];            // start index monotone in t
    const int jmax = tb + TQ - 1;

    for (int j = jmin; j <= jmax; j++) {
        float4 k4 = *(const float4*)(kb + (size_t)j * DWM + d0);
        float4 v4 = *(const float4*)(vb + (size_t)j * DWM + d0);
        float s[TQ];
#pragma unroll
        for (int i = 0; i < TQ; i++)
            s[i] = q4[i].x * k4.x + q4[i].y * k4.y + q4[i].z * k4.z + q4[i].w * k4.w;
#pragma unroll
        for (int off = 8; off >= 1; off >>= 1)
#pragma unroll
            for (int i = 0; i < TQ; i++)
                s[i] += __shfl_xor_sync(0xffffffffu, s[i], off, 16);

#pragma unroll
        for (int i = 0; i < TQ; i++) {
            int t = tb + i;
            if (j >= st[i] && j <= t) {
                float sc = s[i] * 0.125f;
                float mn = fmaxf(m[i], sc);
                float co = __expf(m[i] - mn);
                float wt = __expf(sc - mn);
                l[i] = l[i] * co + wt;
                acc[i].x = acc[i].x * co + wt * v4.x;
                acc[i].y = acc[i].y * co + wt * v4.y;
                acc[i].z = acc[i].z * co + wt * v4.z;
                acc[i].w = acc[i].w * co + wt * v4.w;
                m[i] = mn;
            }
        }
    }

#pragma unroll
    for (int i = 0; i < TQ; i++) {
        float inv = 1.0f / l[i];
        __half2 p0 = __floats2half2_rn(acc[i].x * inv, acc[i].y * inv);
        __half2 p1 = __floats2half2_rn(acc[i].z * inv, acc[i].w * inv);
        __half2* dst = (__half2*)(ob + (size_t)(tb + i) * DWM + d0);
        dst[0] = p0; dst[1] = p1;
    }
}

// ---------------------------------------------------------------------------
// Launch
// ---------------------------------------------------------------------------
extern "C" void kernel_launch(void* const* d_in, const int* in_sizes, int n_in,
                              void* d_out, int out_size)
{
    const float*         x  = (const float*)d_in[0];
    const unsigned char* rs = (const unsigned char*)d_in[1];
    const float* Wq = (const float*)d_in[2];
    const float* bq = (const float*)d_in[3];
    const float* Wk = (const float*)d_in[4];
    const float* bk = (const float*)d_in[5];
    const float* Wv = (const float*)d_in[6];
    const float* bv = (const float*)d_in[7];
    const float* Wo = (const float*)d_in[8];
    const float* bo = (const float*)d_in[9];
    float* y = (float*)d_out;

    cudaFuncSetAttribute(gemm_fp16_kernel,
                         cudaFuncAttributeMaxDynamicSharedMemorySize, GSMEM);

    prep_kernel<<<1, 256>>>(rs, bq, bk, bv, bo);
    conv_x_kernel<<<32768, 256>>>((const float4*)x);
    conv_w_kernel<<<dim3(1024, 4), 256>>>((const float4*)Wq, (const float4*)Wk,
                                          (const float4*)Wv, (const float4*)Wo);

    // Fused Q,K,V projections: grid.x = 3 weights * 8 bn (bn fast -> A stripe
    // shared by 24 CTAs, weights L2-resident)
    gemm_fp16_kernel<<<dim3(24, 256), 256, GSMEM>>>(nullptr, 0, 0);

    attn_kernel<<<dim3(BSZ, PP / TQ), 256>>>();

    // y = attn_out @ Wo + bo
    gemm_fp16_kernel<<<dim3(8, 256), 256, GSMEM>>>(y, 1, 3);
}